// round 10
// baseline (speedup 1.0000x reference)
#include <cuda_runtime.h>
#include <cuda_bf16.h>
#include <cstdint>
#include <math.h>

// ---------------------------------------------------------------------------
// Problem constants
// ---------------------------------------------------------------------------
#define N 4096
#define D 512
#define NB 151
#define HALFB 75
#define INV_STEP 75.0f

#define BM 128
#define BK 64             // bf16 K per chunk = 128B rows (swizzle atom)
#define NCHUNK (D / BK)   // 8
#define NT (N / BM)       // 32
#define NTILES (NT * (NT + 1) / 2)  // 528
#define NWORK 296                   // 2 persistent CTAs per SM
#define STAGE_BYTES 32768           // 2 tiles (A,B) x 128 rows x 128B

// dynamic smem layout
#define OFF_CLS   0                 // 256 ints = 1024B
#define OFF_HIST  1024              // 16 warps * 2 hsel * 152 u64 = 38912B
#define OFF_TILES 40960
#define SMEM_TOTAL (OFF_TILES + 2 * STAGE_BYTES)   // 106496 (x2 CTA = 212992 <= 228KB)

// ---------------------------------------------------------------------------
// Inline PTX helpers
// ---------------------------------------------------------------------------
__device__ __forceinline__ uint32_t smem_u32(const void* p) {
    uint32_t a;
    asm("{ .reg .u64 t; cvta.to.shared.u64 t, %1; cvt.u32.u64 %0, t; }" : "=r"(a) : "l"(p));
    return a;
}
__device__ __forceinline__ void cp16(uint32_t dst, const void* src) {
    asm volatile("cp.async.cg.shared.global [%0], [%1], 16;" :: "r"(dst), "l"(src) : "memory");
}
__device__ __forceinline__ void cp_commit() {
    asm volatile("cp.async.commit_group;" ::: "memory");
}
__device__ __forceinline__ void cp_wait0() {
    asm volatile("cp.async.wait_group 0;" ::: "memory");
}
__device__ __forceinline__ void ldmx4(uint32_t* r, uint32_t addr) {
    asm volatile("ldmatrix.sync.aligned.m8n8.x4.shared.b16 {%0,%1,%2,%3}, [%4];"
                 : "=r"(r[0]), "=r"(r[1]), "=r"(r[2]), "=r"(r[3]) : "r"(addr));
}
__device__ __forceinline__ void mma16816(float* c, const uint32_t* a, const uint32_t* b) {
    asm volatile("mma.sync.aligned.m16n8k16.row.col.f32.bf16.bf16.f32 "
                 "{%0,%1,%2,%3}, {%4,%5,%6,%7}, {%8,%9}, {%0,%1,%2,%3};"
                 : "+f"(c[0]), "+f"(c[1]), "+f"(c[2]), "+f"(c[3])
                 : "r"(a[0]), "r"(a[1]), "r"(a[2]), "r"(a[3]), "r"(b[0]), "r"(b[1]));
}

// ---------------------------------------------------------------------------
// Scratch (static device memory -- no allocations)
// ---------------------------------------------------------------------------
__device__ __nv_bfloat16 g_bf[(size_t)N * D];
__device__ float g_C[2 * NB];   // counts  (pos, neg)
__device__ float g_G[2 * NB];   // frac sums
__device__ int g_done;

// ---------------------------------------------------------------------------
// Kernel 1: L2-normalize each row into bf16; block 0 also zeroes accum state
// ---------------------------------------------------------------------------
__global__ void norm_kernel(const float* __restrict__ f) {
    int row = blockIdx.x;
    if (row == 0) {
        if (threadIdx.x == 0) g_done = 0;
        for (int b = threadIdx.x; b < 2 * NB; b += 128) { g_C[b] = 0.0f; g_G[b] = 0.0f; }
    }
    const float* src = f + (size_t)row * D;
    float ss = 0.0f;
    for (int k = threadIdx.x; k < D; k += 128) {
        float v = src[k];
        ss += v * v;
    }
    #pragma unroll
    for (int o = 16; o > 0; o >>= 1) ss += __shfl_down_sync(0xffffffffu, ss, o);
    __shared__ float wsum[4];
    if ((threadIdx.x & 31) == 0) wsum[threadIdx.x >> 5] = ss;
    __syncthreads();
    float inv = 1.0f / sqrtf(wsum[0] + wsum[1] + wsum[2] + wsum[3]);
    for (int k = threadIdx.x; k < D; k += 128) {
        g_bf[(size_t)row * D + k] = __float2bfloat16(src[k] * inv);
    }
}

// ---------------------------------------------------------------------------
// decode linear upper-tri tile id -> (rowBase, colBase)
// ---------------------------------------------------------------------------
__device__ __forceinline__ void decode_tile(int t, int& rowBase, int& colBase) {
    int br = 0;
    while (t >= NT - br) { t -= NT - br; br++; }
    rowBase = br * BM;
    colBase = (br + t) * BM;
}

// ---------------------------------------------------------------------------
// Kernel 2: persistent HMMA bf16 f@f^T + fused packed-histogram
// 512 threads = 16 warps, warp grid 4(m) x 4(n), warp tile 32x32
// Histogram contribution per pair: ONE u64 atomicAdd of (1<<40 | fr*2^20)
// at bin lo; hist[b] = C[b] - G[b] + G[b-1] reconstructed at the end.
// ---------------------------------------------------------------------------
__global__ void __launch_bounds__(512, 2) pair_mma_hist_kernel(
        const int* __restrict__ classes, float* __restrict__ out) {
    extern __shared__ char smem[];
    uint32_t sb = smem_u32(smem);
    int tid = threadIdx.x;
    int wid = tid >> 5;
    int lane = tid & 31;

    int* clsS = (int*)(smem + OFF_CLS);
    unsigned long long* histU = (unsigned long long*)(smem + OFF_HIST);
    for (int b = tid; b < 16 * 2 * 152; b += 512) histU[b] = 0ull;

    uint32_t tilesBase = sb + OFF_TILES;
    int ldr = tid >> 3;        // 0..63 row-within-64
    int ldp = tid & 7;         // 16B piece within 128B row

    int wm = wid & 3;
    int wn = wid >> 2;
    int blk = lane >> 3;
    int lrow = lane & 7;

    int tileIdx = blockIdx.x;
    int rowBase, colBase;
    decode_tile(tileIdx, rowBase, colBase);
    const char* gA = (const char*)(g_bf + (size_t)rowBase * D);
    const char* gB = (const char*)(g_bf + (size_t)colBase * D);

    // prologue: issue chunk0 of first tile into stage 0
    #pragma unroll
    for (int it = 0; it < 4; it++) {
        const int tile = it >> 1;
        int r = ((it & 1) << 6) + ldr;
        uint32_t dst = tilesBase + tile * 16384 + r * 128 + ((ldp ^ (r & 7)) << 4);
        const char* src = (tile ? gB : gA) + ((size_t)r * D + ldp * 8) * 2;
        cp16(dst, src);
    }
    cp_commit();

    while (tileIdx < NTILES) {
        int nextTile = tileIdx + NWORK;
        int rowBaseN = 0, colBaseN = 0;
        const char *gAn = gA, *gBn = gB;
        if (nextTile < NTILES) {
            decode_tile(nextTile, rowBaseN, colBaseN);
            gAn = (const char*)(g_bf + (size_t)rowBaseN * D);
            gBn = (const char*)(g_bf + (size_t)colBaseN * D);
        }

        __syncthreads();   // prior epilogue finished reading clsS
        if (tid < 128) clsS[tid] = classes[rowBase + tid];
        else if (tid < 256) clsS[tid] = classes[colBase + tid - 128];

        float acc[2][4][4];
        #pragma unroll
        for (int mi = 0; mi < 2; mi++)
            #pragma unroll
            for (int ni = 0; ni < 4; ni++)
                #pragma unroll
                for (int q = 0; q < 4; q++) acc[mi][ni][q] = 0.0f;

        for (int c = 0; c < NCHUNK; c++) {
            cp_wait0();
            __syncthreads();
            // issue next loads: chunk c+1 of this tile, or chunk0 of next tile
            if (c + 1 < NCHUNK) {
                uint32_t stb = tilesBase + ((c + 1) & 1) * STAGE_BYTES;
                #pragma unroll
                for (int it = 0; it < 4; it++) {
                    const int tile = it >> 1;
                    int r = ((it & 1) << 6) + ldr;
                    uint32_t dst = stb + tile * 16384 + r * 128 + ((ldp ^ (r & 7)) << 4);
                    const char* src = (tile ? gB : gA) +
                                      ((size_t)r * D + (size_t)(c + 1) * BK + ldp * 8) * 2;
                    cp16(dst, src);
                }
            } else if (nextTile < NTILES) {
                #pragma unroll
                for (int it = 0; it < 4; it++) {
                    const int tile = it >> 1;
                    int r = ((it & 1) << 6) + ldr;
                    uint32_t dst = tilesBase + tile * 16384 + r * 128 + ((ldp ^ (r & 7)) << 4);
                    const char* src = (tile ? gBn : gAn) + ((size_t)r * D + ldp * 8) * 2;
                    cp16(dst, src);
                }
            }
            cp_commit();

            uint32_t aBase = tilesBase + (c & 1) * STAGE_BYTES;
            uint32_t bBase = aBase + 16384;

            #pragma unroll
            for (int ks = 0; ks < 4; ks++) {
                uint32_t af[2][4], bfr[4][2];
                #pragma unroll
                for (int mi = 0; mi < 2; mi++) {
                    int row = wm * 32 + mi * 16 + ((blk & 1) << 3) + lrow;
                    int piece = ks * 2 + (blk >> 1);
                    ldmx4(af[mi], aBase + row * 128 + ((piece ^ (row & 7)) << 4));
                }
                #pragma unroll
                for (int ni2 = 0; ni2 < 2; ni2++) {
                    int row = wn * 32 + ni2 * 16 + ((blk >> 1) << 3) + lrow;
                    int piece = ks * 2 + (blk & 1);
                    uint32_t r4[4];
                    ldmx4(r4, bBase + row * 128 + ((piece ^ (row & 7)) << 4));
                    bfr[ni2 * 2][0] = r4[0]; bfr[ni2 * 2][1] = r4[1];
                    bfr[ni2 * 2 + 1][0] = r4[2]; bfr[ni2 * 2 + 1][1] = r4[3];
                }
                #pragma unroll
                for (int mi = 0; mi < 2; mi++)
                    #pragma unroll
                    for (int ni = 0; ni < 4; ni++)
                        mma16816(acc[mi][ni], af[mi], bfr[ni]);
            }
        }

        // ---- fused epilogue: ONE packed u64 atomic per pair ----
        unsigned long long* hw = histU + wid * 2 * 152;
        int iBase = rowBase + wm * 32 + (lane >> 2);
        int jBase = colBase + wn * 32 + (lane & 3) * 2;
        const int* clsB = clsS + 128;
        bool offDiag = (rowBase != colBase);

        #pragma unroll
        for (int mi = 0; mi < 2; mi++) {
            int i0 = iBase + mi * 16;
            int ci0 = clsS[i0 - rowBase];
            int ci1 = clsS[i0 + 8 - rowBase];
            #pragma unroll
            for (int ni = 0; ni < 4; ni++) {
                int j0 = jBase + ni * 8;
                int cj0 = clsB[j0 - colBase];
                int cj1 = clsB[j0 + 1 - colBase];
                #pragma unroll
                for (int q = 0; q < 4; q++) {
                    int i = i0 + ((q >> 1) << 3);
                    int j = j0 + (q & 1);
                    if (offDiag || i < j) {
                        int ci = (q & 2) ? ci1 : ci0;
                        int cj = (q & 1) ? cj1 : cj0;
                        float x = acc[mi][ni][q] * INV_STEP;
                        float kf = floorf(x);
                        float fr = x - kf;
                        int lo = (int)kf + HALFB;
                        if (lo < 0) { lo = 0; fr = 0.0f; }
                        else if (lo > NB - 2) { lo = NB - 2; fr = 1.0f; }
                        unsigned long long p =
                            (1ull << 40) | (unsigned long long)__float2uint_rn(fr * 1048576.0f);
                        int hsel = (ci == cj) ? 0 : 1;
                        atomicAdd(&hw[hsel * 152 + lo], p);
                    }
                }
            }
        }

        tileIdx = nextTile;
        rowBase = rowBaseN; colBase = colBaseN;
        gA = gAn; gB = gBn;
    }

    // ---- flush: unpack 16 copies, accumulate C and G to global ----
    __syncthreads();
    for (int b = tid; b < 2 * NB; b += 512) {
        int hsel = b / NB;
        int idx = b - hsel * NB;
        float cnt = 0.0f, frs = 0.0f;
        #pragma unroll
        for (int cpy = 0; cpy < 16; cpy++) {
            unsigned long long p = histU[(cpy * 2 + hsel) * 152 + idx];
            cnt += (float)(unsigned int)(p >> 40);
            frs += (float)(p & 0xFFFFFFFFFFull);
        }
        atomicAdd(&g_C[b], cnt);
        atomicAdd(&g_G[b], frs * (1.0f / 1048576.0f));
    }

    // ---- last CTA finalizes ----
    __threadfence();
    __shared__ int isLast;
    if (tid == 0) {
        int old = atomicAdd(&g_done, 1);
        isLast = (old == NWORK - 1) ? 1 : 0;
    }
    __syncthreads();
    if (!isLast) return;

    float* sp = (float*)(smem + OFF_HIST);     // reuse smem
    float* sn = sp + 152;
    float* acc2 = sp + 304;
    if (tid < NB) {
        float gp_m1 = (tid > 0) ? g_G[tid - 1] : 0.0f;
        float gn_m1 = (tid > 0) ? g_G[NB + tid - 1] : 0.0f;
        sp[tid] = g_C[tid] - g_G[tid] + gp_m1;
        sn[tid] = g_C[NB + tid] - g_G[NB + tid] + gn_m1;
    }
    if (tid == 0) { acc2[0] = 0.0f; acc2[1] = 0.0f; }
    __syncthreads();
    for (int off = 1; off < NB; off <<= 1) {
        float v = 0.0f;
        if (tid < NB && tid >= off) v = sp[tid - off];
        __syncthreads();
        if (tid < NB && tid >= off) sp[tid] += v;
        __syncthreads();
    }
    if (tid < NB) {
        atomicAdd(&acc2[0], sn[tid]);
        atomicAdd(&acc2[1], sn[tid] * sp[tid]);
    }
    __syncthreads();
    if (tid == 0) out[0] = acc2[1] / (sp[NB - 1] * acc2[0]);
}

// ---------------------------------------------------------------------------
extern "C" void kernel_launch(void* const* d_in, const int* in_sizes, int n_in,
                              void* d_out, int out_size) {
    const float* features = (const float*)d_in[0];
    const int*   classes  = (const int*)d_in[1];
    float*       out      = (float*)d_out;

    cudaFuncSetAttribute(pair_mma_hist_kernel,
                         cudaFuncAttributeMaxDynamicSharedMemorySize, SMEM_TOTAL);

    norm_kernel<<<N, 128>>>(features);
    pair_mma_hist_kernel<<<NWORK, 512, SMEM_TOTAL>>>(classes, out);
}

// round 11
// speedup vs baseline: 2.6857x; 2.6857x over previous
#include <cuda_runtime.h>
#include <cuda_bf16.h>
#include <cstdint>
#include <math.h>

// ---------------------------------------------------------------------------
// Problem constants
// ---------------------------------------------------------------------------
#define N 4096
#define D 512
#define NB 151
#define HALFB 75
#define INV_STEP 75.0f

#define BM 128
#define BK 64             // bf16 K per chunk = 128B rows (swizzle atom)
#define NCHUNK (D / BK)   // 8
#define NT (N / BM)       // 32
#define NTILES (NT * (NT + 1) / 2)  // 528
#define NWORK 296                   // 2 persistent CTAs per SM
#define STAGE_BYTES 32768           // 2 tiles (A,B) x 128 rows x 128B

// dynamic smem layout
#define OFF_CLS   0                 // 256 ints = 1024B
#define OFF_HIST  1024              // 32 copies * 2 hsel * 152 u32 = 38912B
#define OFF_TILES 40960
#define SMEM_TOTAL (OFF_TILES + 2 * STAGE_BYTES)   // 106496 (x2 CTA fits 228KB)

// ---------------------------------------------------------------------------
// Inline PTX helpers
// ---------------------------------------------------------------------------
__device__ __forceinline__ uint32_t smem_u32(const void* p) {
    uint32_t a;
    asm("{ .reg .u64 t; cvta.to.shared.u64 t, %1; cvt.u32.u64 %0, t; }" : "=r"(a) : "l"(p));
    return a;
}
__device__ __forceinline__ void cp16(uint32_t dst, const void* src) {
    asm volatile("cp.async.cg.shared.global [%0], [%1], 16;" :: "r"(dst), "l"(src) : "memory");
}
__device__ __forceinline__ void cp_commit() {
    asm volatile("cp.async.commit_group;" ::: "memory");
}
__device__ __forceinline__ void cp_wait0() {
    asm volatile("cp.async.wait_group 0;" ::: "memory");
}
__device__ __forceinline__ void ldmx4(uint32_t* r, uint32_t addr) {
    asm volatile("ldmatrix.sync.aligned.m8n8.x4.shared.b16 {%0,%1,%2,%3}, [%4];"
                 : "=r"(r[0]), "=r"(r[1]), "=r"(r[2]), "=r"(r[3]) : "r"(addr));
}
__device__ __forceinline__ void mma16816(float* c, const uint32_t* a, const uint32_t* b) {
    asm volatile("mma.sync.aligned.m16n8k16.row.col.f32.bf16.bf16.f32 "
                 "{%0,%1,%2,%3}, {%4,%5,%6,%7}, {%8,%9}, {%0,%1,%2,%3};"
                 : "+f"(c[0]), "+f"(c[1]), "+f"(c[2]), "+f"(c[3])
                 : "r"(a[0]), "r"(a[1]), "r"(a[2]), "r"(a[3]), "r"(b[0]), "r"(b[1]));
}

// ---------------------------------------------------------------------------
// Scratch (static device memory -- no allocations)
// ---------------------------------------------------------------------------
__device__ __nv_bfloat16 g_bf[(size_t)N * D];
__device__ float g_C[2 * NB];   // counts  (pos, neg)
__device__ float g_G[2 * NB];   // frac sums
__device__ int g_done;

// ---------------------------------------------------------------------------
// Kernel 1: L2-normalize each row into bf16; block 0 also zeroes accum state
// ---------------------------------------------------------------------------
__global__ void norm_kernel(const float* __restrict__ f) {
    int row = blockIdx.x;
    if (row == 0) {
        if (threadIdx.x == 0) g_done = 0;
        for (int b = threadIdx.x; b < 2 * NB; b += 128) { g_C[b] = 0.0f; g_G[b] = 0.0f; }
    }
    const float* src = f + (size_t)row * D;
    float ss = 0.0f;
    for (int k = threadIdx.x; k < D; k += 128) {
        float v = src[k];
        ss += v * v;
    }
    #pragma unroll
    for (int o = 16; o > 0; o >>= 1) ss += __shfl_down_sync(0xffffffffu, ss, o);
    __shared__ float wsum[4];
    if ((threadIdx.x & 31) == 0) wsum[threadIdx.x >> 5] = ss;
    __syncthreads();
    float inv = 1.0f / sqrtf(wsum[0] + wsum[1] + wsum[2] + wsum[3]);
    for (int k = threadIdx.x; k < D; k += 128) {
        g_bf[(size_t)row * D + k] = __float2bfloat16(src[k] * inv);
    }
}

// ---------------------------------------------------------------------------
// decode linear upper-tri tile id -> (rowBase, colBase)
// ---------------------------------------------------------------------------
__device__ __forceinline__ void decode_tile(int t, int& rowBase, int& colBase) {
    int br = 0;
    while (t >= NT - br) { t -= NT - br; br++; }
    rowBase = br * BM;
    colBase = (br + t) * BM;
}

// ---------------------------------------------------------------------------
// Kernel 2: persistent HMMA bf16 f@f^T + fused packed-u32 histogram
// 512 threads = 16 warps, warp grid 4(m) x 4(n), warp tile 32x32
// Per pair: ONE u32 atomicAdd of (1<<21 | round(fr*255)) at bin lo.
// 32 histogram copies (warp x lane-parity) -> per-copy max 1024 pairs,
// so count*2^21 + fracsum < 2^31 + 2^18: no overflow possible.
// hist[b] = C[b] - G[b] + G[b-1] reconstructed at the end.
// ---------------------------------------------------------------------------
__global__ void __launch_bounds__(512, 2) pair_mma_hist_kernel(
        const int* __restrict__ classes, float* __restrict__ out) {
    extern __shared__ char smem[];
    uint32_t sb = smem_u32(smem);
    int tid = threadIdx.x;
    int wid = tid >> 5;
    int lane = tid & 31;

    int* clsS = (int*)(smem + OFF_CLS);
    unsigned int* histU = (unsigned int*)(smem + OFF_HIST);
    for (int b = tid; b < 32 * 2 * 152; b += 512) histU[b] = 0u;

    uint32_t tilesBase = sb + OFF_TILES;
    int ldr = tid >> 3;        // 0..63 row-within-64
    int ldp = tid & 7;         // 16B piece within 128B row

    int wm = wid & 3;
    int wn = wid >> 2;
    int blk = lane >> 3;
    int lrow = lane & 7;

    int tileIdx = blockIdx.x;
    int rowBase, colBase;
    decode_tile(tileIdx, rowBase, colBase);
    const char* gA = (const char*)(g_bf + (size_t)rowBase * D);
    const char* gB = (const char*)(g_bf + (size_t)colBase * D);

    // prologue: issue chunk0 of first tile into stage 0
    #pragma unroll
    for (int it = 0; it < 4; it++) {
        const int tile = it >> 1;
        int r = ((it & 1) << 6) + ldr;
        uint32_t dst = tilesBase + tile * 16384 + r * 128 + ((ldp ^ (r & 7)) << 4);
        const char* src = (tile ? gB : gA) + ((size_t)r * D + ldp * 8) * 2;
        cp16(dst, src);
    }
    cp_commit();

    while (tileIdx < NTILES) {
        int nextTile = tileIdx + NWORK;
        int rowBaseN = 0, colBaseN = 0;
        const char *gAn = gA, *gBn = gB;
        if (nextTile < NTILES) {
            decode_tile(nextTile, rowBaseN, colBaseN);
            gAn = (const char*)(g_bf + (size_t)rowBaseN * D);
            gBn = (const char*)(g_bf + (size_t)colBaseN * D);
        }

        __syncthreads();   // prior epilogue finished reading clsS
        if (tid < 128) clsS[tid] = classes[rowBase + tid];
        else if (tid < 256) clsS[tid] = classes[colBase + tid - 128];

        float acc[2][4][4];
        #pragma unroll
        for (int mi = 0; mi < 2; mi++)
            #pragma unroll
            for (int ni = 0; ni < 4; ni++)
                #pragma unroll
                for (int q = 0; q < 4; q++) acc[mi][ni][q] = 0.0f;

        for (int c = 0; c < NCHUNK; c++) {
            cp_wait0();
            __syncthreads();
            // issue next loads: chunk c+1 of this tile, or chunk0 of next tile
            if (c + 1 < NCHUNK) {
                uint32_t stb = tilesBase + ((c + 1) & 1) * STAGE_BYTES;
                #pragma unroll
                for (int it = 0; it < 4; it++) {
                    const int tile = it >> 1;
                    int r = ((it & 1) << 6) + ldr;
                    uint32_t dst = stb + tile * 16384 + r * 128 + ((ldp ^ (r & 7)) << 4);
                    const char* src = (tile ? gB : gA) +
                                      ((size_t)r * D + (size_t)(c + 1) * BK + ldp * 8) * 2;
                    cp16(dst, src);
                }
            } else if (nextTile < NTILES) {
                #pragma unroll
                for (int it = 0; it < 4; it++) {
                    const int tile = it >> 1;
                    int r = ((it & 1) << 6) + ldr;
                    uint32_t dst = tilesBase + tile * 16384 + r * 128 + ((ldp ^ (r & 7)) << 4);
                    const char* src = (tile ? gBn : gAn) + ((size_t)r * D + ldp * 8) * 2;
                    cp16(dst, src);
                }
            }
            cp_commit();

            uint32_t aBase = tilesBase + (c & 1) * STAGE_BYTES;
            uint32_t bBase = aBase + 16384;

            #pragma unroll
            for (int ks = 0; ks < 4; ks++) {
                uint32_t af[2][4], bfr[4][2];
                #pragma unroll
                for (int mi = 0; mi < 2; mi++) {
                    int row = wm * 32 + mi * 16 + ((blk & 1) << 3) + lrow;
                    int piece = ks * 2 + (blk >> 1);
                    ldmx4(af[mi], aBase + row * 128 + ((piece ^ (row & 7)) << 4));
                }
                #pragma unroll
                for (int ni2 = 0; ni2 < 2; ni2++) {
                    int row = wn * 32 + ni2 * 16 + ((blk >> 1) << 3) + lrow;
                    int piece = ks * 2 + (blk & 1);
                    uint32_t r4[4];
                    ldmx4(r4, bBase + row * 128 + ((piece ^ (row & 7)) << 4));
                    bfr[ni2 * 2][0] = r4[0]; bfr[ni2 * 2][1] = r4[1];
                    bfr[ni2 * 2 + 1][0] = r4[2]; bfr[ni2 * 2 + 1][1] = r4[3];
                }
                #pragma unroll
                for (int mi = 0; mi < 2; mi++)
                    #pragma unroll
                    for (int ni = 0; ni < 4; ni++)
                        mma16816(acc[mi][ni], af[mi], bfr[ni]);
            }
        }

        // ---- fused epilogue: ONE packed u32 atomic per pair ----
        unsigned int* hw = histU + (wid * 2 + (lane & 1)) * 2 * 152;
        int iBase = rowBase + wm * 32 + (lane >> 2);
        int jBase = colBase + wn * 32 + (lane & 3) * 2;
        const int* clsB = clsS + 128;
        bool offDiag = (rowBase != colBase);

        #pragma unroll
        for (int mi = 0; mi < 2; mi++) {
            int i0 = iBase + mi * 16;
            int ci0 = clsS[i0 - rowBase];
            int ci1 = clsS[i0 + 8 - rowBase];
            #pragma unroll
            for (int ni = 0; ni < 4; ni++) {
                int j0 = jBase + ni * 8;
                int cj0 = clsB[j0 - colBase];
                int cj1 = clsB[j0 + 1 - colBase];
                #pragma unroll
                for (int q = 0; q < 4; q++) {
                    int i = i0 + ((q >> 1) << 3);
                    int j = j0 + (q & 1);
                    if (offDiag || i < j) {
                        int ci = (q & 2) ? ci1 : ci0;
                        int cj = (q & 1) ? cj1 : cj0;
                        float x = acc[mi][ni][q] * INV_STEP;
                        float kf = floorf(x);
                        float fr = x - kf;
                        int lo = (int)kf + HALFB;
                        if (lo < 0) { lo = 0; fr = 0.0f; }
                        else if (lo > NB - 2) { lo = NB - 2; fr = 1.0f; }
                        unsigned int p = (1u << 21) | __float2uint_rn(fr * 255.0f);
                        int hsel = (ci == cj) ? 0 : 1;
                        atomicAdd(&hw[hsel * 152 + lo], p);
                    }
                }
            }
        }

        tileIdx = nextTile;
        rowBase = rowBaseN; colBase = colBaseN;
        gA = gAn; gB = gBn;
    }

    // ---- flush: unpack 32 copies, accumulate C and G to global ----
    __syncthreads();
    for (int b = tid; b < 2 * NB; b += 512) {
        int hsel = b / NB;
        int idx = b - hsel * NB;
        unsigned int cnt = 0;
        unsigned int frs = 0;
        #pragma unroll
        for (int cpy = 0; cpy < 32; cpy++) {
            unsigned int p = histU[(cpy * 2 + hsel) * 152 + idx];
            cnt += p >> 21;
            frs += p & 0x1FFFFFu;
        }
        atomicAdd(&g_C[b], (float)cnt);
        atomicAdd(&g_G[b], (float)frs * (1.0f / 255.0f));
    }

    // ---- last CTA finalizes ----
    __threadfence();
    __shared__ int isLast;
    if (tid == 0) {
        int old = atomicAdd(&g_done, 1);
        isLast = (old == NWORK - 1) ? 1 : 0;
    }
    __syncthreads();
    if (!isLast) return;

    float* sp = (float*)(smem + OFF_HIST);     // reuse smem
    float* sn = sp + 152;
    float* acc2 = sp + 304;
    if (tid < NB) {
        float gp_m1 = (tid > 0) ? g_G[tid - 1] : 0.0f;
        float gn_m1 = (tid > 0) ? g_G[NB + tid - 1] : 0.0f;
        sp[tid] = g_C[tid] - g_G[tid] + gp_m1;
        sn[tid] = g_C[NB + tid] - g_G[NB + tid] + gn_m1;
    }
    if (tid == 0) { acc2[0] = 0.0f; acc2[1] = 0.0f; }
    __syncthreads();
    for (int off = 1; off < NB; off <<= 1) {
        float v = 0.0f;
        if (tid < NB && tid >= off) v = sp[tid - off];
        __syncthreads();
        if (tid < NB && tid >= off) sp[tid] += v;
        __syncthreads();
    }
    if (tid < NB) {
        atomicAdd(&acc2[0], sn[tid]);
        atomicAdd(&acc2[1], sn[tid] * sp[tid]);
    }
    __syncthreads();
    if (tid == 0) out[0] = acc2[1] / (sp[NB - 1] * acc2[0]);
}

// ---------------------------------------------------------------------------
extern "C" void kernel_launch(void* const* d_in, const int* in_sizes, int n_in,
                              void* d_out, int out_size) {
    const float* features = (const float*)d_in[0];
    const int*   classes  = (const int*)d_in[1];
    float*       out      = (float*)d_out;

    cudaFuncSetAttribute(pair_mma_hist_kernel,
                         cudaFuncAttributeMaxDynamicSharedMemorySize, SMEM_TOTAL);

    norm_kernel<<<N, 128>>>(features);
    pair_mma_hist_kernel<<<NWORK, 512, SMEM_TOTAL>>>(classes, out);
}